// round 15
// baseline (speedup 1.0000x reference)
#include <cuda_runtime.h>
#include <cuda_fp16.h>
#include <cstdint>
#include <math.h>

// Problem constants (fixed shapes)
#define SDIM   2048
#define LDIM   3
#define DDIM   128
#define NKDIM  16
#define VOC    50000
#define NTOK   (SDIM*LDIM)      // 6144
#define NPART  48               // 6144 / 128

// GEMM config: persistent CTAs, 128-row M-stripe resident, B streamed 64-col tiles
#define GT_N    64
#define N_NT    782             // 50048 / 64
#define NPADV   (N_NT*GT_N)     // 50048
#define NSLOT   27              // 27 slots x 16 stripes = 432 CTAs = 3/SM
#define NSTRIPE 16              // 2048 / 128
#define ROWB    272             // 256B row (128 fp16) + 16B pad, ldmatrix conflict-free
#define A_SZ    (128*ROWB)      // 34816
#define B_SZ    (GT_N*ROWB)     // 17408
#define OFF_A   0
#define OFF_B   A_SZ            // two B buffers
#define SMEM_TOTAL (A_SZ + 2*B_SZ)   // 69632 -> 3 CTAs/SM

// k_mid batching
#define MPOS  16
#define FCIN  (NKDIM + LDIM*DDIM)   // 400
#define NJ4   (FCIN/4)              // 100

// ---------------- device scratch (static, allocation-free) ----------------
__device__ float g_partial[NPART*DDIM];
__device__ float g_c[VOC];                  // c[v] = fc2b[v] + Eu . fc2W[v,:128]
__device__ float4 g_W1T4[NJ4*DDIM];         // fc1W repacked: [j4][e] -> 4 consecutive j
__device__ uint4 g_Ah4[SDIM*128*2/16];      // u_attn fp16 [s][k]
__device__ uint4 g_Bh4[(size_t)NPADV*128*2/16];   // w2 fp16 [v][k]

__device__ __forceinline__ uint32_t smem_u32(const void* p){
    uint32_t a;
    asm("{ .reg .u64 t; cvta.to.shared.u64 t, %1; cvt.u32.u64 %0, t; }" : "=r"(a) : "l"(p));
    return a;
}
__device__ __forceinline__ void cp_async16(uint32_t dst, const void* src){
    asm volatile("cp.async.cg.shared.global [%0], [%1], 16;" :: "r"(dst), "l"(src));
}
#define CP_COMMIT() asm volatile("cp.async.commit_group;" ::: "memory")
#define CP_WAIT(n)  asm volatile("cp.async.wait_group %0;" :: "n"(n) : "memory")

__device__ __forceinline__ void ldsm_x4(uint32_t (&r)[4], uint32_t addr){
    asm volatile("ldmatrix.sync.aligned.m8n8.x4.shared.b16 {%0,%1,%2,%3}, [%4];"
        : "=r"(r[0]), "=r"(r[1]), "=r"(r[2]), "=r"(r[3]) : "r"(addr));
}
__device__ __forceinline__ void mma16816(float (&d)[4], const uint32_t (&a)[4],
                                         uint32_t b0, uint32_t b1){
    asm volatile(
        "mma.sync.aligned.m16n8k16.row.col.f32.f16.f16.f32 "
        "{%0,%1,%2,%3}, {%4,%5,%6,%7}, {%8,%9}, {%0,%1,%2,%3};"
        : "+f"(d[0]), "+f"(d[1]), "+f"(d[2]), "+f"(d[3])
        : "r"(a[0]), "r"(a[1]), "r"(a[2]), "r"(a[3]), "r"(b0), "r"(b1));
}
__device__ __forceinline__ unsigned short h_bits(__half h){
    return __half_as_ushort(h);
}

// ---------------- Eu partial sums + fc1W repack (merged) ----------------
// blocks [0, NPART): Eu partials (first 128 threads only).
// blocks [NPART, NPART+50): repack fc1W into [j4][e] layout.
__global__ void k_eu_partial(const int* __restrict__ su, const float* __restrict__ emb,
                             const float* __restrict__ fc1W){
    const int tid = threadIdx.x;
    if (blockIdx.x >= NPART){
        int idx = (blockIdx.x - NPART)*256 + tid;   // 50*256 = 12800 >= 12800
        if (idx < NJ4*DDIM){
            int e = idx & 127, j4 = idx >> 7;
            const float* src = fc1W + (size_t)e*FCIN + j4*4;
            g_W1T4[j4*DDIM + e] = make_float4(src[0], src[1], src[2], src[3]);
        }
        return;
    }
    __shared__ int sIdx[128];
    if (tid < 128) sIdx[tid] = su[blockIdx.x*128 + tid];
    __syncthreads();
    if (tid >= 128) return;
    float sum = 0.f;
    #pragma unroll 4
    for (int t = 0; t < 128; t++)
        sum += emb[(size_t)sIdx[t]*DDIM + tid];
    g_partial[blockIdx.x*DDIM + tid] = sum;
}

// ---------------- middle network: 16 positions per CTA ----------------
// Reference attention collapses: attn[i,d] == Ec[i,d] (softmax rows sum to 1
// under the reference broadcasting), so fc1 input = [conv(16) | Ec(384)].
__global__ void __launch_bounds__(128) k_mid(
    const int*  __restrict__ su,   const float* __restrict__ emb,
    const float* __restrict__ convK, const float* __restrict__ convb,
    const float* __restrict__ fc1b)
{
    const int bx  = blockIdx.x;
    const int tid = threadIdx.x;
    const int w   = tid >> 5, lane = tid & 31;

    __shared__ float sIn[MPOS][FCIN];
    __shared__ float sH[MPOS][DDIM];
    __shared__ float sMM[4][MPOS][2];
    __shared__ float sEu[DDIM];

    {
        float s = 0.f;
        #pragma unroll
        for (int b = 0; b < NPART; b++) s += g_partial[b*DDIM + tid];
        sEu[tid] = s * (1.0f / (float)NTOK);
    }

    #pragma unroll
    for (int p = 0; p < MPOS; p++){
        int s = bx*MPOS + p;
        #pragma unroll
        for (int l = 0; l < LDIM; l++)
            sIn[p][NKDIM + l*DDIM + tid] = emb[(size_t)su[s*LDIM + l]*DDIM + tid];
    }
    __syncthreads();

    #pragma unroll
    for (int kk = 0; kk < 4; kk++){
        int k = w*4 + kk;
        float ck[12];
        #pragma unroll
        for (int j = 0; j < 12; j++) ck[j] = convK[k*(LDIM*DDIM) + lane + j*32];
        float cb = convb[k];
        #pragma unroll
        for (int p = 0; p < MPOS; p++){
            float acc = 0.f;
            #pragma unroll
            for (int j = 0; j < 12; j++)
                acc += ck[j] * sIn[p][NKDIM + lane + j*32];
            #pragma unroll
            for (int o = 16; o; o >>= 1) acc += __shfl_xor_sync(0xffffffffu, acc, o);
            if (lane == 0) sIn[p][k] = fmaxf(acc + cb, 0.f);
        }
    }
    __syncthreads();

    // fc1 via repacked W1T4: coalesced float4 per thread, broadcast sIn reads
    float acc[MPOS];
    {
        float bias = fc1b[tid];
        #pragma unroll
        for (int p = 0; p < MPOS; p++) acc[p] = bias;
        #pragma unroll 2
        for (int j4 = 0; j4 < NJ4; j4++){
            float4 a = g_W1T4[j4*DDIM + tid];
            #pragma unroll
            for (int p = 0; p < MPOS; p++){
                float4 in = *(const float4*)&sIn[p][j4*4];
                acc[p] = fmaf(a.x,in.x,fmaf(a.y,in.y,fmaf(a.z,in.z,fmaf(a.w,in.w,acc[p]))));
            }
        }
    }
    #pragma unroll
    for (int p = 0; p < MPOS; p++){
        float h = fmaxf(acc[p], 0.f);
        sH[p][tid] = h;
        float mx = h, mn = h;
        #pragma unroll
        for (int o = 16; o; o >>= 1){
            mx = fmaxf(mx, __shfl_xor_sync(0xffffffffu, mx, o));
            mn = fminf(mn, __shfl_xor_sync(0xffffffffu, mn, o));
        }
        if (lane == 0){ sMM[w][p][0] = mx; sMM[w][p][1] = mn; }
    }
    __syncthreads();

    float a = sEu[tid];
    #pragma unroll
    for (int p = 0; p < MPOS; p++){
        float hmax = fmaxf(fmaxf(sMM[0][p][0],sMM[1][p][0]), fmaxf(sMM[2][p][0],sMM[3][p][0]));
        float hmin = fminf(fminf(sMM[0][p][1],sMM[1][p][1]), fminf(sMM[2][p][1],sMM[3][p][1]));
        float m = (a > 0.f) ? a*hmax : a*hmin;
        float den = 0.f, num = 0.f;
        #pragma unroll 8
        for (int q = 0; q < DDIM; q++){
            float hq = sH[p][q];
            float t = __expf(fmaf(a, hq, -m));
            den += t;
            num = fmaf(t, hq, num);
        }
        float u = num/den;
        int s = bx*MPOS + p;
        ((__half*)g_Ah4)[s*128 + tid] = __float2half(u);
    }
}

// ---------------- merged prep: c[v] + B fp16 convert; 32 v per CTA ----------------
__global__ void __launch_bounds__(256) k_prep(const float* __restrict__ fc2W,
                                              const float* __restrict__ fc2b){
    __shared__ float sEu[DDIM];
    const int tid = threadIdx.x;
    const int v0  = blockIdx.x * 32;

    if (tid < DDIM){
        float s = 0.f;
        #pragma unroll
        for (int b = 0; b < NPART; b++) s += g_partial[b*DDIM + tid];
        sEu[tid] = s * (1.0f / (float)NTOK);
    }
    __syncthreads();

    // c[v] = fc2b[v] + Eu . fc2W[v,:128]  (warp per v, 4 rounds)
    {
        const int w = tid >> 5, lane = tid & 31;
        float4 ee = *(const float4*)(sEu + lane*4);
        #pragma unroll
        for (int r = 0; r < 4; r++){
            int v = v0 + w*4 + r;
            if (v < VOC){
                float4 ww = *(const float4*)(fc2W + (size_t)v*256 + lane*4);
                float acc = ww.x*ee.x + ww.y*ee.y + ww.z*ee.z + ww.w*ee.w;
                #pragma unroll
                for (int o = 16; o; o >>= 1) acc += __shfl_xor_sync(0xffffffffu, acc, o);
                if (lane == 0) g_c[v] = acc + fc2b[v];
            }
        }
    }

    // fp16 convert of fc2W[:,128:256]: thread -> (v, 16 k's)
    {
        int v  = v0 + (tid >> 3);
        int ko = (tid & 7) * 16;
        unsigned long long* bh = (unsigned long long*)g_Bh4 + ((size_t)v*128 + ko)/4;
        #pragma unroll
        for (int j = 0; j < 4; j++){
            float4 b = (v < VOC) ? *(const float4*)(fc2W + (size_t)v*256 + 128 + ko + j*4)
                                 : make_float4(0.f,0.f,0.f,0.f);
            unsigned long long hp =
                  (unsigned long long)h_bits(__float2half(b.x))
                | ((unsigned long long)h_bits(__float2half(b.y)) << 16)
                | ((unsigned long long)h_bits(__float2half(b.z)) << 32)
                | ((unsigned long long)h_bits(__float2half(b.w)) << 48);
            bh[j] = hp;
        }
    }
}

// ---------------- persistent GEMM: single-pass fp16 mma.sync ----------------
// out[s,v] = c[v] + a.b  (fp16 inputs, f32 accum)
// grid (NSLOT, NSTRIPE): blockIdx.y = 128-row M-stripe (A resident in SMEM),
// blockIdx.x = N slot; walks n-tiles slot, slot+NSLOT, ... double-buffered B.
// 3 CTAs/SM (24 warps, 6/SMSP); frag double-buffer in regs; c loads hoisted.
__global__ void __launch_bounds__(256, 3) k_gemm(float* __restrict__ out){
    extern __shared__ char smem[];
    const uint32_t sb = smem_u32(smem);
    const int t = threadIdx.x;
    const int m_base = blockIdx.y * 128;

    // resident A stripe (128 rows x 256B)
    {
        const char* gA = (const char*)g_Ah4 + (size_t)m_base*256;
        #pragma unroll
        for (int i = 0; i < 8; i++){
            int idx = i*256 + t, r = idx >> 4, c = idx & 15;
            cp_async16(sb + OFF_A + r*ROWB + c*16, gA + (size_t)idx*16);
        }
    }
    // first B tile into buffer 0
    int nt = blockIdx.x;
    {
        const char* gB = (const char*)g_Bh4 + (size_t)nt*GT_N*256;
        #pragma unroll
        for (int i = 0; i < 4; i++){
            int idx = i*256 + t, r = idx >> 4, c = idx & 15;
            cp_async16(sb + OFF_B + r*ROWB + c*16, gB + (size_t)idx*16);
        }
    }
    CP_COMMIT();
    CP_WAIT(0);
    __syncthreads();

    const int lane = t & 31, wid = t >> 5;
    const int wm = wid >> 1, wn = wid & 1;            // 4m x 2n warps -> 32x32 tiles
    const uint32_t lmo = (uint32_t)((lane & 15)*ROWB + (lane >> 4)*16);
    const uint32_t aW = sb + OFF_A + (uint32_t)(wm*32*ROWB) + lmo;
    const uint32_t bW0 = sb + OFF_B + (uint32_t)(wn*32*ROWB) + lmo;
    const int gID = lane >> 2, tig = lane & 3;

    int cur = 0;
    while (nt < N_NT){
        int nnt = nt + NSLOT;
        if (nnt < N_NT){
            uint32_t dst = sb + OFF_B + (uint32_t)((cur^1)*B_SZ);
            const char* gB = (const char*)g_Bh4 + (size_t)nnt*GT_N*256;
            #pragma unroll
            for (int i = 0; i < 4; i++){
                int idx = i*256 + t, r = idx >> 4, c = idx & 15;
                cp_async16(dst + r*ROWB + c*16, gB + (size_t)idx*16);
            }
        }
        CP_COMMIT();

        // hoisted epilogue bias loads: latency hidden behind MMA loop
        float2 cc[4];
        int vbase[4];
        #pragma unroll
        for (int n8 = 0; n8 < 4; n8++){
            int v = nt*GT_N + wn*32 + n8*8 + tig*2;
            vbase[n8] = v;
            cc[n8] = (v < VOC) ? *(const float2*)(g_c + v) : make_float2(0.f, 0.f);
        }

        float acc[2][4][4];
        #pragma unroll
        for (int mi = 0; mi < 2; mi++)
            #pragma unroll
            for (int n8 = 0; n8 < 4; n8++)
                #pragma unroll
                for (int q = 0; q < 4; q++) acc[mi][n8][q] = 0.f;

        // software-pipelined inner loop: frag double buffer
        {
            const uint32_t bW = bW0 + (uint32_t)(cur*B_SZ);
            uint32_t ua[2][2][4], ub[2][2][4];
            #pragma unroll
            for (int mi = 0; mi < 2; mi++) ldsm_x4(ua[0][mi], aW + mi*16*ROWB);
            #pragma unroll
            for (int nj = 0; nj < 2; nj++) ldsm_x4(ub[0][nj], bW + nj*16*ROWB);
            #pragma unroll
            for (int ks = 0; ks < 8; ks++){
                int cb = ks & 1, nb = cb ^ 1;
                if (ks < 7){
                    uint32_t off = (uint32_t)((ks+1)*32);
                    #pragma unroll
                    for (int mi = 0; mi < 2; mi++) ldsm_x4(ua[nb][mi], aW + mi*16*ROWB + off);
                    #pragma unroll
                    for (int nj = 0; nj < 2; nj++) ldsm_x4(ub[nb][nj], bW + nj*16*ROWB + off);
                }
                #pragma unroll
                for (int mi = 0; mi < 2; mi++)
                    #pragma unroll
                    for (int n8 = 0; n8 < 4; n8++)
                        mma16816(acc[mi][n8], ua[cb][mi],
                                 ub[cb][n8>>1][n8&1], ub[cb][n8>>1][2+(n8&1)]);
            }
        }

        // epilogue: add hoisted c, float2 stores
        #pragma unroll
        for (int n8 = 0; n8 < 4; n8++){
            int v = vbase[n8];
            if (v < VOC){
                #pragma unroll
                for (int mi = 0; mi < 2; mi++){
                    int r0 = m_base + wm*32 + mi*16 + gID;
                    float2 d0 = { acc[mi][n8][0] + cc[n8].x, acc[mi][n8][1] + cc[n8].y };
                    float2 d1 = { acc[mi][n8][2] + cc[n8].x, acc[mi][n8][3] + cc[n8].y };
                    *(float2*)(out + (size_t)r0*VOC + v)     = d0;
                    *(float2*)(out + (size_t)(r0+8)*VOC + v) = d1;
                }
            }
        }

        CP_WAIT(0);
        __syncthreads();
        cur ^= 1;
        nt = nnt;
    }
}

// ---------------- launch ----------------
extern "C" void kernel_launch(void* const* d_in, const int* in_sizes, int n_in,
                              void* d_out, int out_size){
    const int*   su    = (const int*)  d_in[0];
    const float* emb   = (const float*)d_in[1];
    const float* convK = (const float*)d_in[2];
    const float* convb = (const float*)d_in[3];
    const float* fc1W  = (const float*)d_in[7];
    const float* fc1b  = (const float*)d_in[8];
    const float* fc2W  = (const float*)d_in[9];
    const float* fc2b  = (const float*)d_in[10];
    float* out = (float*)d_out;

    (void)in_sizes; (void)n_in; (void)out_size;

    cudaFuncSetAttribute(k_gemm, cudaFuncAttributeMaxDynamicSharedMemorySize, SMEM_TOTAL);

    k_eu_partial<<<NPART + 50, 256>>>(su, emb, fc1W);
    k_mid<<<SDIM/MPOS, 128>>>(su, emb, convK, convb, fc1b);
    k_prep<<<NPADV/32, 256>>>(fc2W, fc2b);
    k_gemm<<<dim3(NSLOT, NSTRIPE), 256, SMEM_TOTAL>>>(out);
}

// round 16
// speedup vs baseline: 1.0965x; 1.0965x over previous
#include <cuda_runtime.h>
#include <cuda_fp16.h>
#include <cstdint>
#include <math.h>

// Problem constants (fixed shapes)
#define SDIM   2048
#define LDIM   3
#define DDIM   128
#define NKDIM  16
#define VOC    50000
#define NTOK   (SDIM*LDIM)      // 6144
#define NPART  48               // 6144 / 128

// GEMM config: persistent CTAs, 128-row M-stripe resident, B streamed 64-col tiles
#define GT_N    64
#define N_NT    782             // 50048 / 64
#define NPADV   (N_NT*GT_N)     // 50048
#define NSLOT   27              // 27 slots x 16 stripes = 432 CTAs = 3/SM
#define NSTRIPE 16              // 2048 / 128
#define ROWB    272             // 256B row (128 fp16) + 16B pad, ldmatrix conflict-free
#define A_SZ    (128*ROWB)      // 34816
#define B_SZ    (GT_N*ROWB)     // 17408
#define OFF_A   0
#define OFF_B   A_SZ            // two B buffers
#define SMEM_TOTAL (A_SZ + 2*B_SZ)   // 69632 -> 3 CTAs/SM

// k_mid batching: 4 positions/CTA -> 512 CTAs (~14 warps/SM, latency-hiding)
#define MPOS  4
#define FCIN  (NKDIM + LDIM*DDIM)   // 400
#define NJ4   (FCIN/4)              // 100

// ---------------- device scratch (static, allocation-free) ----------------
__device__ float g_partial[NPART*DDIM];
__device__ float g_c[VOC];                  // c[v] = fc2b[v] + Eu . fc2W[v,:128]
__device__ float4 g_W1T4[NJ4*DDIM];         // fc1W repacked: [j4][e] -> 4 consecutive j
__device__ uint4 g_Ah4[SDIM*128*2/16];      // u_attn fp16 [s][k]
__device__ uint4 g_Bh4[(size_t)NPADV*128*2/16];   // w2 fp16 [v][k]

__device__ __forceinline__ uint32_t smem_u32(const void* p){
    uint32_t a;
    asm("{ .reg .u64 t; cvta.to.shared.u64 t, %1; cvt.u32.u64 %0, t; }" : "=r"(a) : "l"(p));
    return a;
}
__device__ __forceinline__ void cp_async16(uint32_t dst, const void* src){
    asm volatile("cp.async.cg.shared.global [%0], [%1], 16;" :: "r"(dst), "l"(src));
}
#define CP_COMMIT() asm volatile("cp.async.commit_group;" ::: "memory")
#define CP_WAIT(n)  asm volatile("cp.async.wait_group %0;" :: "n"(n) : "memory")

__device__ __forceinline__ void ldsm_x4(uint32_t (&r)[4], uint32_t addr){
    asm volatile("ldmatrix.sync.aligned.m8n8.x4.shared.b16 {%0,%1,%2,%3}, [%4];"
        : "=r"(r[0]), "=r"(r[1]), "=r"(r[2]), "=r"(r[3]) : "r"(addr));
}
__device__ __forceinline__ void mma16816(float (&d)[4], const uint32_t (&a)[4],
                                         uint32_t b0, uint32_t b1){
    asm volatile(
        "mma.sync.aligned.m16n8k16.row.col.f32.f16.f16.f32 "
        "{%0,%1,%2,%3}, {%4,%5,%6,%7}, {%8,%9}, {%0,%1,%2,%3};"
        : "+f"(d[0]), "+f"(d[1]), "+f"(d[2]), "+f"(d[3])
        : "r"(a[0]), "r"(a[1]), "r"(a[2]), "r"(a[3]), "r"(b0), "r"(b1));
}
__device__ __forceinline__ unsigned short h_bits(__half h){
    return __half_as_ushort(h);
}

// ---------------- Eu partial sums + fc1W repack (merged) ----------------
// blocks [0, NPART): Eu partials (first 128 threads only).
// blocks [NPART, NPART+50): repack fc1W into [j4][e] layout.
__global__ void k_eu_partial(const int* __restrict__ su, const float* __restrict__ emb,
                             const float* __restrict__ fc1W){
    const int tid = threadIdx.x;
    if (blockIdx.x >= NPART){
        int idx = (blockIdx.x - NPART)*256 + tid;   // 50*256 = 12800 >= 12800
        if (idx < NJ4*DDIM){
            int e = idx & 127, j4 = idx >> 7;
            const float* src = fc1W + (size_t)e*FCIN + j4*4;
            g_W1T4[j4*DDIM + e] = make_float4(src[0], src[1], src[2], src[3]);
        }
        return;
    }
    __shared__ int sIdx[128];
    if (tid < 128) sIdx[tid] = su[blockIdx.x*128 + tid];
    __syncthreads();
    if (tid >= 128) return;
    float sum = 0.f;
    #pragma unroll 4
    for (int t = 0; t < 128; t++)
        sum += emb[(size_t)sIdx[t]*DDIM + tid];
    g_partial[blockIdx.x*DDIM + tid] = sum;
}

// ---------------- middle network: 4 positions per CTA, 512 CTAs ----------------
// Reference attention collapses: attn[i,d] == Ec[i,d] (softmax rows sum to 1
// under the reference broadcasting), so fc1 input = [conv(16) | Ec(384)].
__global__ void __launch_bounds__(128) k_mid(
    const int*  __restrict__ su,   const float* __restrict__ emb,
    const float* __restrict__ convK, const float* __restrict__ convb,
    const float* __restrict__ fc1b)
{
    const int bx  = blockIdx.x;
    const int tid = threadIdx.x;
    const int w   = tid >> 5, lane = tid & 31;

    __shared__ float sIn[MPOS][FCIN];
    __shared__ float sH[MPOS][DDIM];
    __shared__ float sMM[4][MPOS][2];
    __shared__ float sEu[DDIM];

    {
        float s = 0.f;
        #pragma unroll
        for (int b = 0; b < NPART; b++) s += g_partial[b*DDIM + tid];
        sEu[tid] = s * (1.0f / (float)NTOK);
    }

    #pragma unroll
    for (int p = 0; p < MPOS; p++){
        int s = bx*MPOS + p;
        #pragma unroll
        for (int l = 0; l < LDIM; l++)
            sIn[p][NKDIM + l*DDIM + tid] = emb[(size_t)su[s*LDIM + l]*DDIM + tid];
    }
    __syncthreads();

    #pragma unroll
    for (int kk = 0; kk < 4; kk++){
        int k = w*4 + kk;
        float ck[12];
        #pragma unroll
        for (int j = 0; j < 12; j++) ck[j] = convK[k*(LDIM*DDIM) + lane + j*32];
        float cb = convb[k];
        #pragma unroll
        for (int p = 0; p < MPOS; p++){
            float acc = 0.f;
            #pragma unroll
            for (int j = 0; j < 12; j++)
                acc += ck[j] * sIn[p][NKDIM + lane + j*32];
            #pragma unroll
            for (int o = 16; o; o >>= 1) acc += __shfl_xor_sync(0xffffffffu, acc, o);
            if (lane == 0) sIn[p][k] = fmaxf(acc + cb, 0.f);
        }
    }
    __syncthreads();

    // fc1 via repacked W1T4: coalesced float4 per thread, broadcast sIn reads
    float acc[MPOS];
    {
        float bias = fc1b[tid];
        #pragma unroll
        for (int p = 0; p < MPOS; p++) acc[p] = bias;
        #pragma unroll 4
        for (int j4 = 0; j4 < NJ4; j4++){
            float4 a = g_W1T4[j4*DDIM + tid];
            #pragma unroll
            for (int p = 0; p < MPOS; p++){
                float4 in = *(const float4*)&sIn[p][j4*4];
                acc[p] = fmaf(a.x,in.x,fmaf(a.y,in.y,fmaf(a.z,in.z,fmaf(a.w,in.w,acc[p]))));
            }
        }
    }
    #pragma unroll
    for (int p = 0; p < MPOS; p++){
        float h = fmaxf(acc[p], 0.f);
        sH[p][tid] = h;
        float mx = h, mn = h;
        #pragma unroll
        for (int o = 16; o; o >>= 1){
            mx = fmaxf(mx, __shfl_xor_sync(0xffffffffu, mx, o));
            mn = fminf(mn, __shfl_xor_sync(0xffffffffu, mn, o));
        }
        if (lane == 0){ sMM[w][p][0] = mx; sMM[w][p][1] = mn; }
    }
    __syncthreads();

    float a = sEu[tid];
    #pragma unroll
    for (int p = 0; p < MPOS; p++){
        float hmax = fmaxf(fmaxf(sMM[0][p][0],sMM[1][p][0]), fmaxf(sMM[2][p][0],sMM[3][p][0]));
        float hmin = fminf(fminf(sMM[0][p][1],sMM[1][p][1]), fminf(sMM[2][p][1],sMM[3][p][1]));
        float m = (a > 0.f) ? a*hmax : a*hmin;
        float den = 0.f, num = 0.f;
        #pragma unroll 8
        for (int q = 0; q < DDIM; q++){
            float hq = sH[p][q];
            float t = __expf(fmaf(a, hq, -m));
            den += t;
            num = fmaf(t, hq, num);
        }
        float u = num/den;
        int s = bx*MPOS + p;
        ((__half*)g_Ah4)[s*128 + tid] = __float2half(u);
    }
}

// ---------------- merged prep: c[v] + B fp16 convert; 32 v per CTA ----------------
__global__ void __launch_bounds__(256) k_prep(const float* __restrict__ fc2W,
                                              const float* __restrict__ fc2b){
    __shared__ float sEu[DDIM];
    const int tid = threadIdx.x;
    const int v0  = blockIdx.x * 32;

    if (tid < DDIM){
        float s = 0.f;
        #pragma unroll
        for (int b = 0; b < NPART; b++) s += g_partial[b*DDIM + tid];
        sEu[tid] = s * (1.0f / (float)NTOK);
    }
    __syncthreads();

    // c[v] = fc2b[v] + Eu . fc2W[v,:128]  (warp per v, 4 rounds)
    {
        const int w = tid >> 5, lane = tid & 31;
        float4 ee = *(const float4*)(sEu + lane*4);
        #pragma unroll
        for (int r = 0; r < 4; r++){
            int v = v0 + w*4 + r;
            if (v < VOC){
                float4 ww = *(const float4*)(fc2W + (size_t)v*256 + lane*4);
                float acc = ww.x*ee.x + ww.y*ee.y + ww.z*ee.z + ww.w*ee.w;
                #pragma unroll
                for (int o = 16; o; o >>= 1) acc += __shfl_xor_sync(0xffffffffu, acc, o);
                if (lane == 0) g_c[v] = acc + fc2b[v];
            }
        }
    }

    // fp16 convert of fc2W[:,128:256]: thread -> (v, 16 k's)
    {
        int v  = v0 + (tid >> 3);
        int ko = (tid & 7) * 16;
        unsigned long long* bh = (unsigned long long*)g_Bh4 + ((size_t)v*128 + ko)/4;
        #pragma unroll
        for (int j = 0; j < 4; j++){
            float4 b = (v < VOC) ? *(const float4*)(fc2W + (size_t)v*256 + 128 + ko + j*4)
                                 : make_float4(0.f,0.f,0.f,0.f);
            unsigned long long hp =
                  (unsigned long long)h_bits(__float2half(b.x))
                | ((unsigned long long)h_bits(__float2half(b.y)) << 16)
                | ((unsigned long long)h_bits(__float2half(b.z)) << 32)
                | ((unsigned long long)h_bits(__float2half(b.w)) << 48);
            bh[j] = hp;
        }
    }
}

// ---------------- persistent GEMM: single-pass fp16 mma.sync ----------------
// out[s,v] = c[v] + a.b  (fp16 inputs, f32 accum)
// grid (NSLOT, NSTRIPE): blockIdx.y = 128-row M-stripe (A resident in SMEM),
// blockIdx.x = N slot; walks n-tiles slot, slot+NSLOT, ... double-buffered B.
// 3 CTAs/SM (24 warps, 6/SMSP); frag double-buffer in regs; c loads hoisted.
__global__ void __launch_bounds__(256, 3) k_gemm(float* __restrict__ out){
    extern __shared__ char smem[];
    const uint32_t sb = smem_u32(smem);
    const int t = threadIdx.x;
    const int m_base = blockIdx.y * 128;

    // resident A stripe (128 rows x 256B)
    {
        const char* gA = (const char*)g_Ah4 + (size_t)m_base*256;
        #pragma unroll
        for (int i = 0; i < 8; i++){
            int idx = i*256 + t, r = idx >> 4, c = idx & 15;
            cp_async16(sb + OFF_A + r*ROWB + c*16, gA + (size_t)idx*16);
        }
    }
    // first B tile into buffer 0
    int nt = blockIdx.x;
    {
        const char* gB = (const char*)g_Bh4 + (size_t)nt*GT_N*256;
        #pragma unroll
        for (int i = 0; i < 4; i++){
            int idx = i*256 + t, r = idx >> 4, c = idx & 15;
            cp_async16(sb + OFF_B + r*ROWB + c*16, gB + (size_t)idx*16);
        }
    }
    CP_COMMIT();
    CP_WAIT(0);
    __syncthreads();

    const int lane = t & 31, wid = t >> 5;
    const int wm = wid >> 1, wn = wid & 1;            // 4m x 2n warps -> 32x32 tiles
    const uint32_t lmo = (uint32_t)((lane & 15)*ROWB + (lane >> 4)*16);
    const uint32_t aW = sb + OFF_A + (uint32_t)(wm*32*ROWB) + lmo;
    const uint32_t bW0 = sb + OFF_B + (uint32_t)(wn*32*ROWB) + lmo;
    const int gID = lane >> 2, tig = lane & 3;

    int cur = 0;
    while (nt < N_NT){
        int nnt = nt + NSLOT;
        if (nnt < N_NT){
            uint32_t dst = sb + OFF_B + (uint32_t)((cur^1)*B_SZ);
            const char* gB = (const char*)g_Bh4 + (size_t)nnt*GT_N*256;
            #pragma unroll
            for (int i = 0; i < 4; i++){
                int idx = i*256 + t, r = idx >> 4, c = idx & 15;
                cp_async16(dst + r*ROWB + c*16, gB + (size_t)idx*16);
            }
        }
        CP_COMMIT();

        // hoisted epilogue bias loads: latency hidden behind MMA loop
        float2 cc[4];
        int vbase[4];
        #pragma unroll
        for (int n8 = 0; n8 < 4; n8++){
            int v = nt*GT_N + wn*32 + n8*8 + tig*2;
            vbase[n8] = v;
            cc[n8] = (v < VOC) ? *(const float2*)(g_c + v) : make_float2(0.f, 0.f);
        }

        float acc[2][4][4];
        #pragma unroll
        for (int mi = 0; mi < 2; mi++)
            #pragma unroll
            for (int n8 = 0; n8 < 4; n8++)
                #pragma unroll
                for (int q = 0; q < 4; q++) acc[mi][n8][q] = 0.f;

        // software-pipelined inner loop: frag double buffer
        {
            const uint32_t bW = bW0 + (uint32_t)(cur*B_SZ);
            uint32_t ua[2][2][4], ub[2][2][4];
            #pragma unroll
            for (int mi = 0; mi < 2; mi++) ldsm_x4(ua[0][mi], aW + mi*16*ROWB);
            #pragma unroll
            for (int nj = 0; nj < 2; nj++) ldsm_x4(ub[0][nj], bW + nj*16*ROWB);
            #pragma unroll
            for (int ks = 0; ks < 8; ks++){
                int cb = ks & 1, nb = cb ^ 1;
                if (ks < 7){
                    uint32_t off = (uint32_t)((ks+1)*32);
                    #pragma unroll
                    for (int mi = 0; mi < 2; mi++) ldsm_x4(ua[nb][mi], aW + mi*16*ROWB + off);
                    #pragma unroll
                    for (int nj = 0; nj < 2; nj++) ldsm_x4(ub[nb][nj], bW + nj*16*ROWB + off);
                }
                #pragma unroll
                for (int mi = 0; mi < 2; mi++)
                    #pragma unroll
                    for (int n8 = 0; n8 < 4; n8++)
                        mma16816(acc[mi][n8], ua[cb][mi],
                                 ub[cb][n8>>1][n8&1], ub[cb][n8>>1][2+(n8&1)]);
            }
        }

        // epilogue: add hoisted c, float2 stores
        #pragma unroll
        for (int n8 = 0; n8 < 4; n8++){
            int v = vbase[n8];
            if (v < VOC){
                #pragma unroll
                for (int mi = 0; mi < 2; mi++){
                    int r0 = m_base + wm*32 + mi*16 + gID;
                    float2 d0 = { acc[mi][n8][0] + cc[n8].x, acc[mi][n8][1] + cc[n8].y };
                    float2 d1 = { acc[mi][n8][2] + cc[n8].x, acc[mi][n8][3] + cc[n8].y };
                    *(float2*)(out + (size_t)r0*VOC + v)     = d0;
                    *(float2*)(out + (size_t)(r0+8)*VOC + v) = d1;
                }
            }
        }

        CP_WAIT(0);
        __syncthreads();
        cur ^= 1;
        nt = nnt;
    }
}

// ---------------- launch ----------------
extern "C" void kernel_launch(void* const* d_in, const int* in_sizes, int n_in,
                              void* d_out, int out_size){
    const int*   su    = (const int*)  d_in[0];
    const float* emb   = (const float*)d_in[1];
    const float* convK = (const float*)d_in[2];
    const float* convb = (const float*)d_in[3];
    const float* fc1W  = (const float*)d_in[7];
    const float* fc1b  = (const float*)d_in[8];
    const float* fc2W  = (const float*)d_in[9];
    const float* fc2b  = (const float*)d_in[10];
    float* out = (float*)d_out;

    (void)in_sizes; (void)n_in; (void)out_size;

    cudaFuncSetAttribute(k_gemm, cudaFuncAttributeMaxDynamicSharedMemorySize, SMEM_TOTAL);

    k_eu_partial<<<NPART + 50, 256>>>(su, emb, fc1W);
    k_mid<<<SDIM/MPOS, 128>>>(su, emb, convK, convb, fc1b);
    k_prep<<<NPADV/32, 256>>>(fc2W, fc2b);
    k_gemm<<<dim3(NSLOT, NSTRIPE), 256, SMEM_TOTAL>>>(out);
}

// round 17
// speedup vs baseline: 1.2072x; 1.1010x over previous
#include <cuda_runtime.h>
#include <cuda_fp16.h>
#include <cstdint>
#include <math.h>

// Problem constants (fixed shapes)
#define SDIM   2048
#define LDIM   3
#define DDIM   128
#define NKDIM  16
#define VOC    50000
#define NTOK   (SDIM*LDIM)      // 6144
#define NPART  96               // 6144 / 64

// GEMM config: persistent CTAs, 128-row M-stripe resident, B streamed 64-col tiles
#define GT_N    64
#define N_NT    782             // 50048 / 64
#define NPADV   (N_NT*GT_N)     // 50048
#define NSLOT   27              // 27 slots x 16 stripes = 432 CTAs = 3/SM
#define NSTRIPE 16              // 2048 / 128
#define ROWB    272             // 256B row (128 fp16) + 16B pad, ldmatrix conflict-free
#define A_SZ    (128*ROWB)      // 34816
#define B_SZ    (GT_N*ROWB)     // 17408
#define OFF_A   0
#define OFF_B   A_SZ            // two B buffers
#define SMEM_TOTAL (A_SZ + 2*B_SZ)   // 69632 -> 3 CTAs/SM

// k_mid batching
#define MPOS  4
#define NMID  (SDIM/MPOS)           // 512
#define FCIN  (NKDIM + LDIM*DDIM)   // 400
#define NJ4   (FCIN/4)              // 100
#define NCVEC 782                   // 64 v per block

// ---------------- device scratch (static, allocation-free) ----------------
__device__ float g_partial[NPART*DDIM];
__device__ float g_c[VOC];                  // c[v] = fc2b[v] + Eu . fc2W[v,:128]
__device__ float4 g_W1T4[NJ4*DDIM];         // fc1W repacked: [j4][e] -> 4 consecutive j
__device__ uint4 g_Ah4[SDIM*128*2/16];      // u_attn fp16 [s][k]
__device__ uint4 g_Bh4[(size_t)NPADV*128*2/16];   // w2 fp16 [v][k]

__device__ __forceinline__ uint32_t smem_u32(const void* p){
    uint32_t a;
    asm("{ .reg .u64 t; cvta.to.shared.u64 t, %1; cvt.u32.u64 %0, t; }" : "=r"(a) : "l"(p));
    return a;
}
__device__ __forceinline__ void cp_async16(uint32_t dst, const void* src){
    asm volatile("cp.async.cg.shared.global [%0], [%1], 16;" :: "r"(dst), "l"(src));
}
#define CP_COMMIT() asm volatile("cp.async.commit_group;" ::: "memory")
#define CP_WAIT(n)  asm volatile("cp.async.wait_group %0;" :: "n"(n) : "memory")

__device__ __forceinline__ void ldsm_x4(uint32_t (&r)[4], uint32_t addr){
    asm volatile("ldmatrix.sync.aligned.m8n8.x4.shared.b16 {%0,%1,%2,%3}, [%4];"
        : "=r"(r[0]), "=r"(r[1]), "=r"(r[2]), "=r"(r[3]) : "r"(addr));
}
__device__ __forceinline__ void mma16816(float (&d)[4], const uint32_t (&a)[4],
                                         uint32_t b0, uint32_t b1){
    asm volatile(
        "mma.sync.aligned.m16n8k16.row.col.f32.f16.f16.f32 "
        "{%0,%1,%2,%3}, {%4,%5,%6,%7}, {%8,%9}, {%0,%1,%2,%3};"
        : "+f"(d[0]), "+f"(d[1]), "+f"(d[2]), "+f"(d[3])
        : "r"(a[0]), "r"(a[1]), "r"(a[2]), "r"(a[3]), "r"(b0), "r"(b1));
}
__device__ __forceinline__ unsigned short h_bits(__half h){
    return __half_as_ushort(h);
}

// ---------------- k1: Eu partials || fc1W repack || B fp16 convert ----------------
// blocks [0, 96): Eu partials, 64 tokens each (two 32-token halves combined in smem)
// blocks [96, 146): fc1W repack into [j4][e]
// blocks [146, 146+1564): fp16 convert of fc2W[:,128:256], 32 v per block
__global__ void __launch_bounds__(256) k1(
    const int* __restrict__ su, const float* __restrict__ emb,
    const float* __restrict__ fc1W, const float* __restrict__ fc2W)
{
    const int tid = threadIdx.x;
    int bx = blockIdx.x;

    if (bx < NPART){
        __shared__ int sIdx[64];
        __shared__ float part[DDIM];
        if (tid < 64) sIdx[tid] = su[bx*64 + tid];
        __syncthreads();
        const int half = tid >> 7, d = tid & 127;
        float s = 0.f;
        #pragma unroll 4
        for (int t = 0; t < 32; t++)
            s += emb[(size_t)sIdx[half*32 + t]*DDIM + d];
        if (half) part[d] = s;
        __syncthreads();
        if (!half) g_partial[bx*DDIM + d] = s + part[d];
        return;
    }
    bx -= NPART;
    if (bx < 50){
        int idx = bx*256 + tid;                     // 50*256 = 12800 >= 12800
        if (idx < NJ4*DDIM){
            int e = idx & 127, j4 = idx >> 7;
            const float* src = fc1W + (size_t)e*FCIN + j4*4;
            g_W1T4[j4*DDIM + e] = make_float4(src[0], src[1], src[2], src[3]);
        }
        return;
    }
    bx -= 50;
    {
        int v0 = bx*32;
        int v  = v0 + (tid >> 3);
        int ko = (tid & 7) * 16;
        unsigned long long* bh = (unsigned long long*)g_Bh4 + ((size_t)v*128 + ko)/4;
        #pragma unroll
        for (int j = 0; j < 4; j++){
            float4 b = (v < VOC) ? *(const float4*)(fc2W + (size_t)v*256 + 128 + ko + j*4)
                                 : make_float4(0.f,0.f,0.f,0.f);
            unsigned long long hp =
                  (unsigned long long)h_bits(__float2half(b.x))
                | ((unsigned long long)h_bits(__float2half(b.y)) << 16)
                | ((unsigned long long)h_bits(__float2half(b.z)) << 32)
                | ((unsigned long long)h_bits(__float2half(b.w)) << 48);
            bh[j] = hp;
        }
    }
}

// ---------------- k2: middle network (512 blocks) || c-vector (782 blocks) ----------------
// Reference attention collapses: attn[i,d] == Ec[i,d] (softmax rows sum to 1
// under the reference broadcasting), so fc1 input = [conv(16) | Ec(384)].
__global__ void __launch_bounds__(128) k2(
    const int*  __restrict__ su,   const float* __restrict__ emb,
    const float* __restrict__ convK, const float* __restrict__ convb,
    const float* __restrict__ fc1b,
    const float* __restrict__ fc2W, const float* __restrict__ fc2b)
{
    const int tid = threadIdx.x;
    const int w   = tid >> 5, lane = tid & 31;
    __shared__ float sEu[DDIM];

    if (blockIdx.x >= NMID){
        // ---- c-vector: 64 v per block ----
        {
            float s = 0.f;
            #pragma unroll
            for (int b = 0; b < NPART; b++) s += g_partial[b*DDIM + tid];
            sEu[tid] = s * (1.0f / (float)NTOK);
        }
        __syncthreads();
        int v0 = (blockIdx.x - NMID)*64;
        float4 ee = *(const float4*)(sEu + lane*4);
        #pragma unroll 4
        for (int r = 0; r < 16; r++){
            int v = v0 + w*16 + r;
            if (v < VOC){
                float4 ww = *(const float4*)(fc2W + (size_t)v*256 + lane*4);
                float acc = ww.x*ee.x + ww.y*ee.y + ww.z*ee.z + ww.w*ee.w;
                #pragma unroll
                for (int o = 16; o; o >>= 1) acc += __shfl_xor_sync(0xffffffffu, acc, o);
                if (lane == 0) g_c[v] = acc + fc2b[v];
            }
        }
        return;
    }

    // ---- middle network: 4 positions per CTA ----
    const int bx = blockIdx.x;
    __shared__ float sIn[MPOS][FCIN];
    __shared__ float sH[MPOS][DDIM];
    __shared__ float sMM[4][MPOS][2];

    {
        float s = 0.f;
        #pragma unroll
        for (int b = 0; b < NPART; b++) s += g_partial[b*DDIM + tid];
        sEu[tid] = s * (1.0f / (float)NTOK);
    }

    #pragma unroll
    for (int p = 0; p < MPOS; p++){
        int s = bx*MPOS + p;
        #pragma unroll
        for (int l = 0; l < LDIM; l++)
            sIn[p][NKDIM + l*DDIM + tid] = emb[(size_t)su[s*LDIM + l]*DDIM + tid];
    }
    __syncthreads();

    #pragma unroll
    for (int kk = 0; kk < 4; kk++){
        int k = w*4 + kk;
        float ck[12];
        #pragma unroll
        for (int j = 0; j < 12; j++) ck[j] = convK[k*(LDIM*DDIM) + lane + j*32];
        float cb = convb[k];
        #pragma unroll
        for (int p = 0; p < MPOS; p++){
            float acc = 0.f;
            #pragma unroll
            for (int j = 0; j < 12; j++)
                acc += ck[j] * sIn[p][NKDIM + lane + j*32];
            #pragma unroll
            for (int o = 16; o; o >>= 1) acc += __shfl_xor_sync(0xffffffffu, acc, o);
            if (lane == 0) sIn[p][k] = fmaxf(acc + cb, 0.f);
        }
    }
    __syncthreads();

    // fc1 via repacked W1T4: coalesced float4 per thread, broadcast sIn reads
    float acc[MPOS];
    {
        float bias = fc1b[tid];
        #pragma unroll
        for (int p = 0; p < MPOS; p++) acc[p] = bias;
        #pragma unroll 4
        for (int j4 = 0; j4 < NJ4; j4++){
            float4 a = g_W1T4[j4*DDIM + tid];
            #pragma unroll
            for (int p = 0; p < MPOS; p++){
                float4 in = *(const float4*)&sIn[p][j4*4];
                acc[p] = fmaf(a.x,in.x,fmaf(a.y,in.y,fmaf(a.z,in.z,fmaf(a.w,in.w,acc[p]))));
            }
        }
    }
    #pragma unroll
    for (int p = 0; p < MPOS; p++){
        float h = fmaxf(acc[p], 0.f);
        sH[p][tid] = h;
        float mx = h, mn = h;
        #pragma unroll
        for (int o = 16; o; o >>= 1){
            mx = fmaxf(mx, __shfl_xor_sync(0xffffffffu, mx, o));
            mn = fminf(mn, __shfl_xor_sync(0xffffffffu, mn, o));
        }
        if (lane == 0){ sMM[w][p][0] = mx; sMM[w][p][1] = mn; }
    }
    __syncthreads();

    float a = sEu[tid];
    #pragma unroll
    for (int p = 0; p < MPOS; p++){
        float hmax = fmaxf(fmaxf(sMM[0][p][0],sMM[1][p][0]), fmaxf(sMM[2][p][0],sMM[3][p][0]));
        float hmin = fminf(fminf(sMM[0][p][1],sMM[1][p][1]), fminf(sMM[2][p][1],sMM[3][p][1]));
        float m = (a > 0.f) ? a*hmax : a*hmin;
        float den = 0.f, num = 0.f;
        #pragma unroll 8
        for (int q = 0; q < DDIM; q++){
            float hq = sH[p][q];
            float t = __expf(fmaf(a, hq, -m));
            den += t;
            num = fmaf(t, hq, num);
        }
        float u = num/den;
        int s = bx*MPOS + p;
        ((__half*)g_Ah4)[s*128 + tid] = __float2half(u);
    }
}

// ---------------- persistent GEMM: single-pass fp16 mma.sync ----------------
// out[s,v] = c[v] + a.b  (fp16 inputs, f32 accum)
// grid (NSLOT, NSTRIPE): blockIdx.y = 128-row M-stripe (A resident in SMEM),
// blockIdx.x = N slot; walks n-tiles slot, slot+NSLOT, ... double-buffered B.
// 3 CTAs/SM (24 warps, 6/SMSP); frag double-buffer in regs; c loads hoisted.
__global__ void __launch_bounds__(256, 3) k_gemm(float* __restrict__ out){
    extern __shared__ char smem[];
    const uint32_t sb = smem_u32(smem);
    const int t = threadIdx.x;
    const int m_base = blockIdx.y * 128;

    // resident A stripe (128 rows x 256B)
    {
        const char* gA = (const char*)g_Ah4 + (size_t)m_base*256;
        #pragma unroll
        for (int i = 0; i < 8; i++){
            int idx = i*256 + t, r = idx >> 4, c = idx & 15;
            cp_async16(sb + OFF_A + r*ROWB + c*16, gA + (size_t)idx*16);
        }
    }
    // first B tile into buffer 0
    int nt = blockIdx.x;
    {
        const char* gB = (const char*)g_Bh4 + (size_t)nt*GT_N*256;
        #pragma unroll
        for (int i = 0; i < 4; i++){
            int idx = i*256 + t, r = idx >> 4, c = idx & 15;
            cp_async16(sb + OFF_B + r*ROWB + c*16, gB + (size_t)idx*16);
        }
    }
    CP_COMMIT();
    CP_WAIT(0);
    __syncthreads();

    const int lane = t & 31, wid = t >> 5;
    const int wm = wid >> 1, wn = wid & 1;            // 4m x 2n warps -> 32x32 tiles
    const uint32_t lmo = (uint32_t)((lane & 15)*ROWB + (lane >> 4)*16);
    const uint32_t aW = sb + OFF_A + (uint32_t)(wm*32*ROWB) + lmo;
    const uint32_t bW0 = sb + OFF_B + (uint32_t)(wn*32*ROWB) + lmo;
    const int gID = lane >> 2, tig = lane & 3;

    int cur = 0;
    while (nt < N_NT){
        int nnt = nt + NSLOT;
        if (nnt < N_NT){
            uint32_t dst = sb + OFF_B + (uint32_t)((cur^1)*B_SZ);
            const char* gB = (const char*)g_Bh4 + (size_t)nnt*GT_N*256;
            #pragma unroll
            for (int i = 0; i < 4; i++){
                int idx = i*256 + t, r = idx >> 4, c = idx & 15;
                cp_async16(dst + r*ROWB + c*16, gB + (size_t)idx*16);
            }
        }
        CP_COMMIT();

        // hoisted epilogue bias loads: latency hidden behind MMA loop
        float2 cc[4];
        int vbase[4];
        #pragma unroll
        for (int n8 = 0; n8 < 4; n8++){
            int v = nt*GT_N + wn*32 + n8*8 + tig*2;
            vbase[n8] = v;
            cc[n8] = (v < VOC) ? *(const float2*)(g_c + v) : make_float2(0.f, 0.f);
        }

        float acc[2][4][4];
        #pragma unroll
        for (int mi = 0; mi < 2; mi++)
            #pragma unroll
            for (int n8 = 0; n8 < 4; n8++)
                #pragma unroll
                for (int q = 0; q < 4; q++) acc[mi][n8][q] = 0.f;

        // software-pipelined inner loop: frag double buffer
        {
            const uint32_t bW = bW0 + (uint32_t)(cur*B_SZ);
            uint32_t ua[2][2][4], ub[2][2][4];
            #pragma unroll
            for (int mi = 0; mi < 2; mi++) ldsm_x4(ua[0][mi], aW + mi*16*ROWB);
            #pragma unroll
            for (int nj = 0; nj < 2; nj++) ldsm_x4(ub[0][nj], bW + nj*16*ROWB);
            #pragma unroll
            for (int ks = 0; ks < 8; ks++){
                int cb = ks & 1, nb = cb ^ 1;
                if (ks < 7){
                    uint32_t off = (uint32_t)((ks+1)*32);
                    #pragma unroll
                    for (int mi = 0; mi < 2; mi++) ldsm_x4(ua[nb][mi], aW + mi*16*ROWB + off);
                    #pragma unroll
                    for (int nj = 0; nj < 2; nj++) ldsm_x4(ub[nb][nj], bW + nj*16*ROWB + off);
                }
                #pragma unroll
                for (int mi = 0; mi < 2; mi++)
                    #pragma unroll
                    for (int n8 = 0; n8 < 4; n8++)
                        mma16816(acc[mi][n8], ua[cb][mi],
                                 ub[cb][n8>>1][n8&1], ub[cb][n8>>1][2+(n8&1)]);
            }
        }

        // epilogue: add hoisted c, float2 stores
        #pragma unroll
        for (int n8 = 0; n8 < 4; n8++){
            int v = vbase[n8];
            if (v < VOC){
                #pragma unroll
                for (int mi = 0; mi < 2; mi++){
                    int r0 = m_base + wm*32 + mi*16 + gID;
                    float2 d0 = { acc[mi][n8][0] + cc[n8].x, acc[mi][n8][1] + cc[n8].y };
                    float2 d1 = { acc[mi][n8][2] + cc[n8].x, acc[mi][n8][3] + cc[n8].y };
                    *(float2*)(out + (size_t)r0*VOC + v)     = d0;
                    *(float2*)(out + (size_t)(r0+8)*VOC + v) = d1;
                }
            }
        }

        CP_WAIT(0);
        __syncthreads();
        cur ^= 1;
        nt = nnt;
    }
}

// ---------------- launch ----------------
extern "C" void kernel_launch(void* const* d_in, const int* in_sizes, int n_in,
                              void* d_out, int out_size){
    const int*   su    = (const int*)  d_in[0];
    const float* emb   = (const float*)d_in[1];
    const float* convK = (const float*)d_in[2];
    const float* convb = (const float*)d_in[3];
    const float* fc1W  = (const float*)d_in[7];
    const float* fc1b  = (const float*)d_in[8];
    const float* fc2W  = (const float*)d_in[9];
    const float* fc2b  = (const float*)d_in[10];
    float* out = (float*)d_out;

    (void)in_sizes; (void)n_in; (void)out_size;

    cudaFuncSetAttribute(k_gemm, cudaFuncAttributeMaxDynamicSharedMemorySize, SMEM_TOTAL);

    k1<<<NPART + 50 + NPADV/32, 256>>>(su, emb, fc1W, fc2W);
    k2<<<NMID + NCVEC, 128>>>(su, emb, convK, convb, fc1b, fc2W, fc2b);
    k_gemm<<<dim3(NSLOT, NSTRIPE), 256, SMEM_TOTAL>>>(out);
}